// round 2
// baseline (speedup 1.0000x reference)
#include <cuda_runtime.h>

// Problem constants
#define BATCH 4096
#define FF    20
#define DD    16
#define HH    2
#define NI    190
#define FD    320        // FF*DD
#define NSPLIT 8         // k-split for W12 partials
#define KCHUNK 40        // 320 / NSPLIT

// Scratch (device globals — no allocations allowed)
__device__ float g_W12p[NSPLIT * FD * NI];  // split-K partials of w1@w2
__device__ float g_W12[FD * NI];            // W12 = w1 @ w2   (320 x 190)
__device__ float g_w[BATCH * NI];           // w  = z @ W12    (4096 x 190)

// ---------------------------------------------------------------------------
// Kernel A1: partial W12[m][n] += sum_{j in chunk} w1[m][j] * w2[j][n]
// grid (5, 3, NSPLIT) : m-tiles of 64, n-tiles of 64, j-chunks of 40
// ---------------------------------------------------------------------------
__global__ __launch_bounds__(256) void k_w12_partial(
    const float* __restrict__ w1, const float* __restrict__ w2)
{
    __shared__ __align__(16) float As[64][KCHUNK];   // [m][j]
    __shared__ __align__(16) float Bs[KCHUNK][64];   // [j][n]
    const int m0 = blockIdx.x * 64;
    const int n0 = blockIdx.y * 64;
    const int j0 = blockIdx.z * KCHUNK;
    const int tid = threadIdx.x;

    for (int e = tid; e < 64 * KCHUNK; e += 256) {
        int m = e / KCHUNK, j = e % KCHUNK;
        As[m][j] = w1[(m0 + m) * FD + j0 + j];
    }
    for (int e = tid; e < KCHUNK * 64; e += 256) {
        int j = e >> 6, n = e & 63;
        int nn = n0 + n;
        Bs[j][n] = (nn < NI) ? w2[(j0 + j) * NI + nn] : 0.f;
    }
    __syncthreads();

    const int ty = tid >> 4;   // 0..15 -> m quad
    const int tx = tid & 15;   // 0..15 -> n quad
    float acc[4][4] = {};
    #pragma unroll
    for (int j = 0; j < KCHUNK; j++) {
        float4 bv = *(const float4*)&Bs[j][tx * 4];
        #pragma unroll
        for (int q = 0; q < 4; q++) {
            float a = As[ty * 4 + q][j];
            acc[q][0] += a * bv.x; acc[q][1] += a * bv.y;
            acc[q][2] += a * bv.z; acc[q][3] += a * bv.w;
        }
    }
    float* dst = g_W12p + blockIdx.z * (FD * NI);
    #pragma unroll
    for (int q = 0; q < 4; q++) {
        int m = m0 + ty * 4 + q;
        #pragma unroll
        for (int r = 0; r < 4; r++) {
            int n = n0 + tx * 4 + r;
            if (n < NI) dst[m * NI + n] = acc[q][r];
        }
    }
}

// ---------------------------------------------------------------------------
// Kernel A2: reduce split-K partials into g_W12
// ---------------------------------------------------------------------------
__global__ __launch_bounds__(256) void k_w12_reduce()
{
    int i = blockIdx.x * 256 + threadIdx.x;
    if (i < FD * NI) {
        float s = 0.f;
        #pragma unroll
        for (int p = 0; p < NSPLIT; p++) s += g_W12p[p * (FD * NI) + i];
        g_W12[i] = s;
    }
}

// ---------------------------------------------------------------------------
// Kernel B: g_w = z @ g_W12   (4096x320 @ 320x190)
// grid (128, 3): 32-batch tiles x 64-n tiles; thread tile 2b x 4n
// ---------------------------------------------------------------------------
__global__ __launch_bounds__(256) void k_senet(const float* __restrict__ z)
{
    __shared__ __align__(16) float Zs[32][33];   // [b][j]  (pad kills store conflicts)
    __shared__ __align__(16) float Ws[32][64];   // [j][n]
    const int b0 = blockIdx.x * 32;
    const int n0 = blockIdx.y * 64;
    const int tid = threadIdx.x;
    const int ty = tid >> 4;   // 0..15 -> b pair
    const int tx = tid & 15;   // 0..15 -> n quad

    float acc[2][4] = {};
    for (int jt = 0; jt < FD; jt += 32) {
        for (int e = tid; e < 32 * 32; e += 256) {
            int bb = e >> 5, j = e & 31;
            Zs[bb][j] = z[(b0 + bb) * FD + jt + j];
        }
        for (int e = tid; e < 32 * 64; e += 256) {
            int j = e >> 6, n = e & 63;
            int nn = n0 + n;
            Ws[j][n] = (nn < NI) ? g_W12[(jt + j) * NI + nn] : 0.f;
        }
        __syncthreads();
        #pragma unroll
        for (int j = 0; j < 32; j++) {
            float4 wv = *(const float4*)&Ws[j][tx * 4];
            #pragma unroll
            for (int q = 0; q < 2; q++) {
                float zv = Zs[ty * 2 + q][j];
                acc[q][0] += zv * wv.x; acc[q][1] += zv * wv.y;
                acc[q][2] += zv * wv.z; acc[q][3] += zv * wv.w;
            }
        }
        __syncthreads();
    }
    #pragma unroll
    for (int q = 0; q < 2; q++) {
        int b = b0 + ty * 2 + q;
        #pragma unroll
        for (int r = 0; r < 4; r++) {
            int n = n0 + tx * 4 + r;
            if (n < NI) g_w[b * NI + n] = acc[q][r];
        }
    }
}

// ---------------------------------------------------------------------------
// Kernel C: per-batch gather + interaction reduce + transform
//   t[f][e] = sum_{k<19} w[II[f][k]] * g[II[f][k]][e]     (e in [0,32))
//   out[b][f][d] = sum_e t[f][e] * Wt[e][d]
// grid 4096, 256 threads
// ---------------------------------------------------------------------------
__global__ __launch_bounds__(256) void k_gather(
    const float* __restrict__ codebook,
    const float* __restrict__ Wt,
    const int*   __restrict__ hash_idx,
    const int*   __restrict__ inter_idx,
    float*       __restrict__ out)
{
    const int b = blockIdx.x;
    const int tid = threadIdx.x;

    __shared__ int   s_idx[2][NI];
    __shared__ int   s_ii[FF * 19];
    __shared__ float s_w[NI];
    __shared__ __align__(16) float s_g[NI][32];   // gathered+concat embedding per combo
    __shared__ __align__(16) float s_t[FF][32];
    __shared__ float s_Wt[32 * 16];

    for (int e = tid; e < 2 * NI; e += 256) {
        int h = e / NI, n = e - h * NI;
        s_idx[h][n] = hash_idx[h * (BATCH * NI) + b * NI + n];
    }
    for (int e = tid; e < FF * 19; e += 256) s_ii[e] = inter_idx[e];
    for (int e = tid; e < NI; e += 256)      s_w[e] = g_w[b * NI + e];
    for (int e = tid; e < 32 * 16; e += 256) s_Wt[e] = Wt[e];
    __syncthreads();

    // Gather 380 codebook rows (16 floats each) as float4s
    for (int u = tid; u < 2 * NI * 4; u += 256) {
        int r = u >> 2, seg = u & 3;
        int h = (r >= NI) ? 1 : 0;
        int n = r - h * NI;
        int idx = s_idx[h][n];
        float4 v = *(const float4*)(codebook + idx * DD + seg * 4);
        *(float4*)&s_g[n][h * DD + seg * 4] = v;
    }
    __syncthreads();

    // Interaction reduce: 20 fields x 8 e-quads = 160 workers
    if (tid < FF * 8) {
        int f = tid >> 3, eq = tid & 7;
        float4 acc = make_float4(0.f, 0.f, 0.f, 0.f);
        #pragma unroll
        for (int k = 0; k < 19; k++) {
            int n = s_ii[f * 19 + k];
            float wv = s_w[n];
            float4 g = *(const float4*)&s_g[n][eq * 4];
            acc.x += wv * g.x; acc.y += wv * g.y;
            acc.z += wv * g.z; acc.w += wv * g.w;
        }
        *(float4*)&s_t[f][eq * 4] = acc;
    }
    __syncthreads();

    // Transform: out[f][d] = sum_e t[f][e] * Wt[e][d]
    for (int o = tid; o < FF * DD; o += 256) {
        int f = o >> 4, d = o & 15;
        float acc = 0.f;
        #pragma unroll
        for (int e = 0; e < 32; e++) acc += s_t[f][e] * s_Wt[e * DD + d];
        out[b * (FF * DD) + f * DD + d] = acc;
    }
}

// ---------------------------------------------------------------------------
extern "C" void kernel_launch(void* const* d_in, const int* in_sizes, int n_in,
                              void* d_out, int out_size)
{
    const float* origin   = (const float*)d_in[0];  // (4096, 20, 16)
    const float* codebook = (const float*)d_in[1];  // (500000, 16)
    const float* Wt       = (const float*)d_in[2];  // (32, 16)
    const float* w1       = (const float*)d_in[3];  // (320, 320)
    const float* w2       = (const float*)d_in[4];  // (320, 190)
    const int*   hash     = (const int*)d_in[5];    // (2, 4096, 190)
    const int*   ii       = (const int*)d_in[6];    // (20, 19)
    float*       out      = (float*)d_out;          // (4096, 20, 16)

    k_w12_partial<<<dim3(5, 3, NSPLIT), 256>>>(w1, w2);
    k_w12_reduce<<<(FD * NI + 255) / 256, 256>>>();
    k_senet<<<dim3(BATCH / 32, 3), 256>>>(origin);
    k_gather<<<BATCH, 256>>>(codebook, Wt, hash, ii, out);
}

// round 3
// speedup vs baseline: 1.0239x; 1.0239x over previous
#include <cuda_runtime.h>

typedef unsigned long long ull;

// Problem constants
#define BATCH 4096
#define FF    20
#define DD    16
#define NI    190
#define FD    320        // FF*DD
#define NP    192        // padded NI pitch for W12
#define NSPLIT 8
#define KCHUNK 40        // 320 / NSPLIT

// Scratch (device globals)
__device__ float g_W12p[NSPLIT * FD * NI];  // split-K partials of w1@w2 (pitch NI)
__device__ float g_W12[FD * NP];            // W12 padded to pitch 192, zeros in pad
__device__ float g_w[BATCH * NI];           // w = z @ W12

// f32x2 packed helpers (sm_100+ PTX)
__device__ __forceinline__ ull fma2(ull a, ull b, ull c) {
    ull d;
    asm("fma.rn.f32x2 %0, %1, %2, %3;" : "=l"(d) : "l"(a), "l"(b), "l"(c));
    return d;
}
__device__ __forceinline__ ull dup2(float x) {
    ull d;
    asm("mov.b64 %0, {%1, %1};" : "=l"(d) : "r"(__float_as_uint(x)));
    return d;
}
__device__ __forceinline__ void unpack2(ull v, float& lo, float& hi) {
    unsigned a, b;
    asm("mov.b64 {%0, %1}, %2;" : "=r"(a), "=r"(b) : "l"(v));
    lo = __uint_as_float(a); hi = __uint_as_float(b);
}

// ---------------------------------------------------------------------------
// Kernel A1: split-K partials of W12 = w1 @ w2
// grid (5, 3, NSPLIT)
// ---------------------------------------------------------------------------
__global__ __launch_bounds__(256) void k_w12_partial(
    const float* __restrict__ w1, const float* __restrict__ w2)
{
    __shared__ __align__(16) float As[64][KCHUNK];
    __shared__ __align__(16) float Bs[KCHUNK][64];
    const int m0 = blockIdx.x * 64;
    const int n0 = blockIdx.y * 64;
    const int j0 = blockIdx.z * KCHUNK;
    const int tid = threadIdx.x;

    for (int e = tid; e < 64 * KCHUNK; e += 256) {
        int m = e / KCHUNK, j = e % KCHUNK;
        As[m][j] = w1[(m0 + m) * FD + j0 + j];
    }
    for (int e = tid; e < KCHUNK * 64; e += 256) {
        int j = e >> 6, n = e & 63;
        int nn = n0 + n;
        Bs[j][n] = (nn < NI) ? w2[(j0 + j) * NI + nn] : 0.f;
    }
    __syncthreads();

    const int ty = tid >> 4;
    const int tx = tid & 15;
    float acc[4][4] = {};
    #pragma unroll
    for (int j = 0; j < KCHUNK; j++) {
        float4 bv = *(const float4*)&Bs[j][tx * 4];
        #pragma unroll
        for (int q = 0; q < 4; q++) {
            float a = As[ty * 4 + q][j];
            acc[q][0] += a * bv.x; acc[q][1] += a * bv.y;
            acc[q][2] += a * bv.z; acc[q][3] += a * bv.w;
        }
    }
    float* dst = g_W12p + blockIdx.z * (FD * NI);
    #pragma unroll
    for (int q = 0; q < 4; q++) {
        int m = m0 + ty * 4 + q;
        #pragma unroll
        for (int r = 0; r < 4; r++) {
            int n = n0 + tx * 4 + r;
            if (n < NI) dst[m * NI + n] = acc[q][r];
        }
    }
}

// ---------------------------------------------------------------------------
// Kernel A2: reduce partials into padded g_W12 (pitch 192, pad = 0)
// ---------------------------------------------------------------------------
__global__ __launch_bounds__(256) void k_w12_reduce()
{
    int i = blockIdx.x * 256 + threadIdx.x;
    if (i < FD * NP) {
        int m = i / NP, c = i - m * NP;
        float s = 0.f;
        if (c < NI) {
            #pragma unroll
            for (int p = 0; p < NSPLIT; p++) s += g_W12p[p * (FD * NI) + m * NI + c];
        }
        g_W12[i] = s;
    }
}

// ---------------------------------------------------------------------------
// Kernel B: g_w = z @ g_W12  (4096x320 @ 320x190), f32x2 packed math
// grid (64, 3): 64-batch x 64-n tiles; thread tile 4b x 4n
// acc packed along n: acc2[r][p] = (out[b_r][n_{2p}], out[b_r][n_{2p+1}])
// ---------------------------------------------------------------------------
__global__ __launch_bounds__(256) void k_senet(const float* __restrict__ z)
{
    __shared__ __align__(16) float Zs[64][36];   // [b][j], pitch 36 (16B-aligned rows)
    __shared__ __align__(16) float Ws[32][64];   // [j][n]
    const int b0 = blockIdx.x * 64;
    const int n0 = blockIdx.y * 64;
    const int tid = threadIdx.x;
    const int ty = tid >> 4;   // 0..15 -> 4-batch group
    const int tx = tid & 15;   // 0..15 -> 4-n group

    ull acc2[4][2] = {};
    for (int jt = 0; jt < FD; jt += 32) {
        // stage Z: 64 rows x 32 j, float4 coalesced
        #pragma unroll
        for (int it = 0; it < 2; it++) {
            int u = tid + it * 256;          // 0..511
            int bb = u >> 3, jq = u & 7;
            float4 v = *(const float4*)&z[(b0 + bb) * FD + jt + jq * 4];
            *(float4*)&Zs[bb][jq * 4] = v;
        }
        // stage W: 32 j x 64 n, float4 from padded pitch-192 W12
        #pragma unroll
        for (int it = 0; it < 2; it++) {
            int u = tid + it * 256;          // 0..511
            int j = u >> 4, nq = u & 15;
            float4 v = *(const float4*)&g_W12[(jt + j) * NP + n0 + nq * 4];
            *(float4*)&Ws[j][nq * 4] = v;
        }
        __syncthreads();
        #pragma unroll
        for (int j = 0; j < 32; j++) {
            ulonglong2 wq = *(const ulonglong2*)&Ws[j][tx * 4];
            #pragma unroll
            for (int r = 0; r < 4; r++) {
                ull zd = dup2(Zs[ty * 4 + r][j]);
                acc2[r][0] = fma2(zd, wq.x, acc2[r][0]);
                acc2[r][1] = fma2(zd, wq.y, acc2[r][1]);
            }
        }
        __syncthreads();
    }
    #pragma unroll
    for (int r = 0; r < 4; r++) {
        int b = b0 + ty * 4 + r;
        float f0, f1, f2, f3;
        unpack2(acc2[r][0], f0, f1);
        unpack2(acc2[r][1], f2, f3);
        float vals[4] = {f0, f1, f2, f3};
        #pragma unroll
        for (int c = 0; c < 4; c++) {
            int n = n0 + tx * 4 + c;
            if (n < NI) g_w[b * NI + n] = vals[c];
        }
    }
}

// ---------------------------------------------------------------------------
// Kernel C: per-batch gather + interaction reduce + transform
// 640 threads (20 warps): warp f owns field f in the reduce (lane = e index)
// ---------------------------------------------------------------------------
__global__ __launch_bounds__(640) void k_gather(
    const float* __restrict__ codebook,
    const float* __restrict__ Wt,
    const int*   __restrict__ hash_idx,
    const int*   __restrict__ inter_idx,
    float*       __restrict__ out)
{
    const int b = blockIdx.x;
    const int tid = threadIdx.x;

    __shared__ int   s_ii[FF * 19];
    __shared__ float s_w[NI];
    __shared__ __align__(16) float s_g[NI][32];  // 128B rows -> conflict-free lane reads
    __shared__ __align__(16) float s_t[FF][32];
    __shared__ float s_Wt[32 * DD];

    // Phase 0 (no barrier dependency with phase 1): small tables
    if (tid < FF * 19) s_ii[tid] = inter_idx[tid];
    if (tid < NI)      s_w[tid] = g_w[b * NI + tid];
    if (tid >= 640 - 512) s_Wt[tid - 128] = Wt[tid - 128];

    // Phase 1: gather 380 codebook rows (2 hashes x 190 combos), 4 float4/row.
    // Each thread loads its own index directly (4 seg-threads hit same address).
    for (int u = tid; u < 2 * NI * 4; u += 640) {
        int r = u >> 2, seg = u & 3;
        int h = (r >= NI) ? 1 : 0;
        int n = r - h * NI;
        int idx = hash_idx[h * (BATCH * NI) + b * NI + n];
        float4 v = *(const float4*)(codebook + idx * DD + seg * 4);
        *(float4*)&s_g[n][h * DD + seg * 4] = v;
    }
    __syncthreads();

    // Phase 2: one warp per field; lane e accumulates t[f][e]
    {
        int f = tid >> 5, lane = tid & 31;
        float acc = 0.f;
        #pragma unroll
        for (int k = 0; k < 19; k++) {
            int n = s_ii[f * 19 + k];
            acc += s_w[n] * s_g[n][lane];
        }
        s_t[f][lane] = acc;
    }
    __syncthreads();

    // Phase 3: out[f][d] = sum_e t[f][e] * Wt[e][d]
    if (tid < FF * DD) {
        int f = tid >> 4, d = tid & 15;
        float acc = 0.f;
        #pragma unroll
        for (int e = 0; e < 32; e++) acc += s_t[f][e] * s_Wt[e * DD + d];
        out[b * (FF * DD) + tid] = acc;
    }
}

// ---------------------------------------------------------------------------
extern "C" void kernel_launch(void* const* d_in, const int* in_sizes, int n_in,
                              void* d_out, int out_size)
{
    const float* origin   = (const float*)d_in[0];  // (4096, 20, 16)
    const float* codebook = (const float*)d_in[1];  // (500000, 16)
    const float* Wt       = (const float*)d_in[2];  // (32, 16)
    const float* w1       = (const float*)d_in[3];  // (320, 320)
    const float* w2       = (const float*)d_in[4];  // (320, 190)
    const int*   hash     = (const int*)d_in[5];    // (2, 4096, 190)
    const int*   ii       = (const int*)d_in[6];    // (20, 19)
    float*       out      = (float*)d_out;          // (4096, 20, 16)

    k_w12_partial<<<dim3(5, 3, NSPLIT), 256>>>(w1, w2);
    k_w12_reduce<<<(FD * NP + 255) / 256, 256>>>();
    k_senet<<<dim3(BATCH / 64, 3), 256>>>(origin);
    k_gather<<<BATCH, 640>>>(codebook, Wt, hash, ii, out);
}